// round 2
// baseline (speedup 1.0000x reference)
#include <cuda_runtime.h>

#define NMAX 50000
#define EMAX 800000
#define HIDDIM 64
#define LN_EPS 1e-5f

// ---------------- scratch (device globals; no allocation allowed) ----------------
__device__ __align__(16) int   g_srcdeg[NMAX];
__device__ __align__(16) int   g_rowcnt[NMAX];
__device__ __align__(16) int   g_cursor[NMAX];
__device__ __align__(16) int   g_rowptr[NMAX + 1];
__device__ __align__(16) float g_dinv[NMAX];
__device__ __align__(16) int2  g_csr[EMAX];              // {src, bitcast(w)} grouped by dst
__device__ __align__(16) float g_H [NMAX * HIDDIM];
__device__ __align__(16) float g_T1[NMAX * HIDDIM];
__device__ __align__(16) float g_T2[NMAX * HIDDIM];
__device__ __align__(16) float g_A [3 * 3 * HIDDIM * HIDDIM];  // folded weights per layer

// ---------------- weight folding: A0 = W0 - W2, A1 = W1, A2 = 2*W2 ----------------
__global__ void prepA_kernel(const float* __restrict__ W) {
    int idx = blockIdx.x * blockDim.x + threadIdx.x;
    if (idx < 3 * 4096) {
        int i = idx >> 12, r = idx & 4095;
        const float* Wi = W + i * 3 * 4096;
        float w0 = Wi[r], w1 = Wi[4096 + r], w2 = Wi[8192 + r];
        float* Ai = g_A + i * 3 * 4096;
        Ai[r]        = w0 - w2;
        Ai[4096 + r] = w1;
        Ai[8192 + r] = 2.0f * w2;
    }
}

__global__ void zero_kernel(int n) {
    int i = blockIdx.x * blockDim.x + threadIdx.x;
    if (i < n) { g_srcdeg[i] = 0; g_rowcnt[i] = 0; g_cursor[i] = 0; }
}

__global__ void count_kernel(const int* __restrict__ src, const int* __restrict__ dst, int e) {
    int i = blockIdx.x * blockDim.x + threadIdx.x;
    if (i < e) {
        atomicAdd(&g_srcdeg[src[i]], 1);
        atomicAdd(&g_rowcnt[dst[i]], 1);
    }
}

__global__ void dinv_kernel(int n) {
    int i = blockIdx.x * blockDim.x + threadIdx.x;
    if (i < n) {
        int d = g_srcdeg[i];
        g_dinv[i] = (d > 0) ? rsqrtf((float)d) : 0.0f;
    }
}

// single-block exclusive scan of g_rowcnt -> g_rowptr
__global__ void scan_kernel(int n) {
    __shared__ int warp_tot[32];
    __shared__ int carry_sh;
    int t = threadIdx.x, lane = t & 31, wid = t >> 5;
    if (t == 0) carry_sh = 0;
    __syncthreads();
    for (int base = 0; base < n; base += 1024) {
        int i = base + t;
        int v = (i < n) ? g_rowcnt[i] : 0;
        int x = v;
        #pragma unroll
        for (int off = 1; off < 32; off <<= 1) {
            int y = __shfl_up_sync(0xffffffffu, x, off);
            if (lane >= off) x += y;
        }
        if (lane == 31) warp_tot[wid] = x;
        __syncthreads();
        if (wid == 0) {
            int wt = warp_tot[lane];
            #pragma unroll
            for (int off = 1; off < 32; off <<= 1) {
                int y = __shfl_up_sync(0xffffffffu, wt, off);
                if (lane >= off) wt += y;
            }
            warp_tot[lane] = wt;
        }
        __syncthreads();
        int wp = (wid > 0) ? warp_tot[wid - 1] : 0;
        if (i < n) g_rowptr[i] = carry_sh + wp + x - v;
        __syncthreads();
        if (t == 0) carry_sh += warp_tot[31];
        __syncthreads();
    }
    if (t == 0) g_rowptr[n] = carry_sh;
}

__global__ void scatter_kernel(const int* __restrict__ src, const int* __restrict__ dst, int e) {
    int i = blockIdx.x * blockDim.x + threadIdx.x;
    if (i < e) {
        int s = src[i], d = dst[i];
        float w = -g_dinv[s] * g_dinv[d];
        int pos = g_rowptr[d] + atomicAdd(&g_cursor[d], 1);
        g_csr[pos] = make_int2(s, __float_as_int(w));
    }
}

// ---------------- SpMM: Y[dst] = sum_e w * X[src]  (16 threads per row) ----------------
// mode 0: X=g_H  -> Y=g_T1 ; mode 1: X=g_T1 -> Y=g_T2
__global__ __launch_bounds__(256) void spmm_kernel(int mode, int n) {
    const float* __restrict__ X = mode ? g_T1 : g_H;
    float* __restrict__ Y       = mode ? g_T2 : g_T1;
    int gid  = blockIdx.x * blockDim.x + threadIdx.x;
    int row  = gid >> 4;
    int lane = gid & 15;
    if (row >= n) return;
    int beg = g_rowptr[row], end = g_rowptr[row + 1];
    float4 a0 = make_float4(0.f, 0.f, 0.f, 0.f);
    float4 a1 = make_float4(0.f, 0.f, 0.f, 0.f);
    int e = beg;
    for (; e + 2 <= end; e += 2) {
        int2 c0 = g_csr[e];
        int2 c1 = g_csr[e + 1];
        float4 v0 = *(const float4*)(X + c0.x * HIDDIM + lane * 4);
        float4 v1 = *(const float4*)(X + c1.x * HIDDIM + lane * 4);
        float w0 = __int_as_float(c0.y), w1 = __int_as_float(c1.y);
        a0.x += w0 * v0.x; a0.y += w0 * v0.y; a0.z += w0 * v0.z; a0.w += w0 * v0.w;
        a1.x += w1 * v1.x; a1.y += w1 * v1.y; a1.z += w1 * v1.z; a1.w += w1 * v1.w;
    }
    if (e < end) {
        int2 c0 = g_csr[e];
        float4 v0 = *(const float4*)(X + c0.x * HIDDIM + lane * 4);
        float w0 = __int_as_float(c0.y);
        a0.x += w0 * v0.x; a0.y += w0 * v0.y; a0.z += w0 * v0.z; a0.w += w0 * v0.w;
    }
    float4 r;
    r.x = a0.x + a1.x; r.y = a0.y + a1.y; r.z = a0.z + a1.z; r.w = a0.w + a1.w;
    *(float4*)(Y + row * HIDDIM + lane * 4) = r;
}

// ---------------- input GEMM: g_H = x @ W_in + b_in  (32 rows/block) ----------------
__global__ __launch_bounds__(256) void ingemm_kernel(const float* __restrict__ x,
                                                     const float* __restrict__ Win,
                                                     const float* __restrict__ bin, int n) {
    __shared__ float sW[16 * 64];
    __shared__ float xt[16 * 33];
    __shared__ float so[32 * 65];
    int t = threadIdx.x, lane = t & 31, wg = t >> 5;
    int row0 = blockIdx.x * 32;
    for (int idx = t; idx < 1024; idx += 256) sW[idx] = Win[idx];
    for (int idx = t; idx < 512; idx += 256) {
        int r = idx >> 4, k = idx & 15;
        int row = row0 + r;
        xt[k * 33 + r] = (row < n) ? x[row * 16 + k] : 0.0f;
    }
    __syncthreads();
    float acc[8] = {0, 0, 0, 0, 0, 0, 0, 0};
    #pragma unroll
    for (int k = 0; k < 16; k++) {
        float xv = xt[k * 33 + lane];
        float4 w0 = *(const float4*)&sW[k * 64 + wg * 8];
        float4 w1 = *(const float4*)&sW[k * 64 + wg * 8 + 4];
        acc[0] += xv * w0.x; acc[1] += xv * w0.y; acc[2] += xv * w0.z; acc[3] += xv * w0.w;
        acc[4] += xv * w1.x; acc[5] += xv * w1.y; acc[6] += xv * w1.z; acc[7] += xv * w1.w;
    }
    #pragma unroll
    for (int u = 0; u < 8; u++) {
        int j = wg * 8 + u;
        so[lane * 65 + j] = acc[u] + bin[j];
    }
    __syncthreads();
    int r = t >> 3, c = (t & 7) * 8;
    int row = row0 + r;
    if (row < n) {
        float4 v0, v1;
        v0.x = so[r*65+c+0]; v0.y = so[r*65+c+1]; v0.z = so[r*65+c+2]; v0.w = so[r*65+c+3];
        v1.x = so[r*65+c+4]; v1.y = so[r*65+c+5]; v1.z = so[r*65+c+6]; v1.w = so[r*65+c+7];
        *(float4*)(g_H + row * 64 + c)     = v0;
        *(float4*)(g_H + row * 64 + c + 4) = v1;
    }
}

// ---------------- fused layer: H = LN(relu(H@A0 + T1@A1 + T2@A2 + cb) + H) ----------------
// NOTE: layer index passed as int; g_A is resolved to a device address INSIDE
// device code (host-side &g_A is the host shadow symbol -> silent garbage on
// GB300 since host memory is ATS-accessible; that was the Round-1 bug).
__global__ __launch_bounds__(256) void layer_kernel(int layer,
                                                    const float* __restrict__ cb,
                                                    const float* __restrict__ lg,
                                                    const float* __restrict__ lbeta, int n) {
    const float* __restrict__ A = g_A + layer * 3 * 4096;
    __shared__ float sA[4096];
    __shared__ float ht[64 * 33];
    __shared__ float tt[64 * 33];
    int t = threadIdx.x, lane = t & 31, wg = t >> 5;
    int row0 = blockIdx.x * 32;
    float acc[8] = {0, 0, 0, 0, 0, 0, 0, 0};

    // ---- pass 0: H @ A0 ----
    for (int idx = t; idx < 1024; idx += 256)
        ((float4*)sA)[idx] = ((const float4*)A)[idx];
    for (int idx = t; idx < 2048; idx += 256) {
        int r = idx >> 6, k = idx & 63;
        int row = row0 + r;
        ht[k * 33 + r] = (row < n) ? g_H[row * 64 + k] : 0.0f;
    }
    __syncthreads();
    #pragma unroll 16
    for (int k = 0; k < 64; k++) {
        float hv = ht[k * 33 + lane];
        float4 w0 = *(const float4*)&sA[k * 64 + wg * 8];
        float4 w1 = *(const float4*)&sA[k * 64 + wg * 8 + 4];
        acc[0] += hv * w0.x; acc[1] += hv * w0.y; acc[2] += hv * w0.z; acc[3] += hv * w0.w;
        acc[4] += hv * w1.x; acc[5] += hv * w1.y; acc[6] += hv * w1.z; acc[7] += hv * w1.w;
    }
    __syncthreads();

    // ---- pass 1: T1 @ A1 ----
    for (int idx = t; idx < 1024; idx += 256)
        ((float4*)sA)[idx] = ((const float4*)(A + 4096))[idx];
    for (int idx = t; idx < 2048; idx += 256) {
        int r = idx >> 6, k = idx & 63;
        int row = row0 + r;
        tt[k * 33 + r] = (row < n) ? g_T1[row * 64 + k] : 0.0f;
    }
    __syncthreads();
    #pragma unroll 16
    for (int k = 0; k < 64; k++) {
        float hv = tt[k * 33 + lane];
        float4 w0 = *(const float4*)&sA[k * 64 + wg * 8];
        float4 w1 = *(const float4*)&sA[k * 64 + wg * 8 + 4];
        acc[0] += hv * w0.x; acc[1] += hv * w0.y; acc[2] += hv * w0.z; acc[3] += hv * w0.w;
        acc[4] += hv * w1.x; acc[5] += hv * w1.y; acc[6] += hv * w1.z; acc[7] += hv * w1.w;
    }
    __syncthreads();

    // ---- pass 2: T2raw @ A2 ----
    for (int idx = t; idx < 1024; idx += 256)
        ((float4*)sA)[idx] = ((const float4*)(A + 8192))[idx];
    for (int idx = t; idx < 2048; idx += 256) {
        int r = idx >> 6, k = idx & 63;
        int row = row0 + r;
        tt[k * 33 + r] = (row < n) ? g_T2[row * 64 + k] : 0.0f;
    }
    __syncthreads();
    #pragma unroll 16
    for (int k = 0; k < 64; k++) {
        float hv = tt[k * 33 + lane];
        float4 w0 = *(const float4*)&sA[k * 64 + wg * 8];
        float4 w1 = *(const float4*)&sA[k * 64 + wg * 8 + 4];
        acc[0] += hv * w0.x; acc[1] += hv * w0.y; acc[2] += hv * w0.z; acc[3] += hv * w0.w;
        acc[4] += hv * w1.x; acc[5] += hv * w1.y; acc[6] += hv * w1.z; acc[7] += hv * w1.w;
    }
    __syncthreads();

    // ---- epilogue: bias + relu + residual, stage to shared ----
    float* so = tt;  // reuse
    #pragma unroll
    for (int u = 0; u < 8; u++) {
        int j = wg * 8 + u;
        float v = fmaxf(acc[u] + cb[j], 0.0f) + ht[j * 33 + lane];
        so[lane * 65 + j] = v;
    }
    __syncthreads();

    // ---- layernorm (8 threads per row) + coalesced store ----
    int r = t >> 3, c = (t & 7) * 8;
    float v[8];
    #pragma unroll
    for (int u = 0; u < 8; u++) v[u] = so[r * 65 + c + u];
    float s = 0.0f;
    #pragma unroll
    for (int u = 0; u < 8; u++) s += v[u];
    #pragma unroll
    for (int m = 1; m < 8; m <<= 1) s += __shfl_xor_sync(0xffffffffu, s, m);
    float mu = s * (1.0f / 64.0f);
    float q = 0.0f;
    #pragma unroll
    for (int u = 0; u < 8; u++) { float d = v[u] - mu; q += d * d; }
    #pragma unroll
    for (int m = 1; m < 8; m <<= 1) q += __shfl_xor_sync(0xffffffffu, q, m);
    float rs = rsqrtf(q * (1.0f / 64.0f) + LN_EPS);
    int row = row0 + r;
    if (row < n) {
        float o[8];
        #pragma unroll
        for (int u = 0; u < 8; u++)
            o[u] = (v[u] - mu) * rs * lg[c + u] + lbeta[c + u];
        float4 o0 = make_float4(o[0], o[1], o[2], o[3]);
        float4 o1 = make_float4(o[4], o[5], o[6], o[7]);
        *(float4*)(g_H + row * 64 + c)     = o0;
        *(float4*)(g_H + row * 64 + c + 4) = o1;
    }
}

// ---------------- output GEMM: out = H @ W_out + b_out ----------------
__global__ __launch_bounds__(256) void outgemm_kernel(const float* __restrict__ Wout,
                                                      const float* __restrict__ bout,
                                                      float* __restrict__ out, int n) {
    __shared__ float hs[64 * 65];
    __shared__ float sW[256];
    __shared__ float sb[4];
    int t = threadIdx.x;
    int row0 = blockIdx.x * 64;
    if (t < 256) sW[t] = Wout[t];
    if (t < 4) sb[t] = bout[t];
    for (int idx = t; idx < 4096; idx += 256) {
        int r = idx >> 6, k = idx & 63;
        int row = row0 + r;
        hs[r * 65 + k] = (row < n) ? g_H[row * 64 + k] : 0.0f;
    }
    __syncthreads();
    int r = t >> 2, j = t & 3;
    float acc = 0.0f;
    #pragma unroll 16
    for (int k = 0; k < 64; k++) acc += hs[r * 65 + k] * sW[k * 4 + j];
    int row = row0 + r;
    if (row < n) out[row * 4 + j] = acc + sb[j];
}

// ---------------- launch ----------------
extern "C" void kernel_launch(void* const* d_in, const int* in_sizes, int n_in,
                              void* d_out, int out_size) {
    // Robust input resolution by element count (dict order preserved for the
    // three 192-element params: cheb_b, ln_g, ln_b).
    const float *x = 0, *Win = 0, *bin = 0, *chW = 0, *Wout = 0, *bout = 0;
    const float *p192[3] = {0, 0, 0};
    const int* ei = 0;
    int n192 = 0, e2 = 0, nx = 0;
    for (int i = 0; i < n_in; i++) {
        int sz = in_sizes[i];
        if      (sz == 1600000) { ei = (const int*)d_in[i]; e2 = sz; }
        else if (sz == 800000)  { x = (const float*)d_in[i]; nx = sz; }
        else if (sz == 1024)    Win  = (const float*)d_in[i];
        else if (sz == 64)      bin  = (const float*)d_in[i];
        else if (sz == 36864)   chW  = (const float*)d_in[i];
        else if (sz == 256)     Wout = (const float*)d_in[i];
        else if (sz == 4)       bout = (const float*)d_in[i];
        else if (sz == 192 && n192 < 3) p192[n192++] = (const float*)d_in[i];
    }
    const float* chb = p192[0];
    const float* lng = p192[1];
    const float* lnb = p192[2];
    float* out = (float*)d_out;

    int n = nx / 16;
    int e = e2 / 2;
    const int* src = ei;
    const int* dst = ei + e;

    // graph preprocessing (CSR by dst) + weight folding
    prepA_kernel<<<(3 * 4096 + 255) / 256, 256>>>(chW);
    zero_kernel<<<(n + 255) / 256, 256>>>(n);
    count_kernel<<<(e + 255) / 256, 256>>>(src, dst, e);
    dinv_kernel<<<(n + 255) / 256, 256>>>(n);
    scan_kernel<<<1, 1024>>>(n);
    scatter_kernel<<<(e + 255) / 256, 256>>>(src, dst, e);

    int gemm_blocks = (n + 31) / 32;
    int spmm_blocks = (n * 16 + 255) / 256;
    int out_blocks  = (n + 63) / 64;

    ingemm_kernel<<<gemm_blocks, 256>>>(x, Win, bin, n);
    for (int i = 0; i < 3; i++) {
        spmm_kernel<<<spmm_blocks, 256>>>(0, n);  // T1 = L_hat @ H
        spmm_kernel<<<spmm_blocks, 256>>>(1, n);  // T2 = L_hat @ T1
        layer_kernel<<<gemm_blocks, 256>>>(i, chb + i * 64, lng + i * 64, lnb + i * 64, n);
    }
    outgemm_kernel<<<out_blocks, 256>>>(Wout, bout, out, n);
}

// round 3
// speedup vs baseline: 1.0509x; 1.0509x over previous
#include <cuda_runtime.h>

#define NMAX 50000
#define EMAX 800000
#define HIDDIM 64
#define LN_EPS 1e-5f

// ---------------- scratch (device globals; no allocation allowed) ----------------
__device__ __align__(16) int   g_srcdeg[NMAX];
__device__ __align__(16) int   g_rowcnt[NMAX];
__device__ __align__(16) int   g_cursor[NMAX];
__device__ __align__(16) int   g_rowptr[NMAX + 1];
__device__ __align__(16) float g_dinv[NMAX];
__device__ __align__(16) int2  g_csr[EMAX];              // {src, bitcast(w)} grouped by dst
__device__ __align__(16) float g_H [NMAX * HIDDIM];
__device__ __align__(16) float g_T1[NMAX * HIDDIM];
__device__ __align__(16) float g_T2[NMAX * HIDDIM];
__device__ __align__(16) float g_A [3 * 3 * HIDDIM * HIDDIM];  // folded weights per layer

// ---------------- f32x2 packed-FMA helpers (sm_100+ PTX) ----------------
__device__ __forceinline__ unsigned long long pack2(float a, float b) {
    unsigned long long r;
    asm("mov.b64 %0, {%1, %2};" : "=l"(r) : "f"(a), "f"(b));
    return r;
}
__device__ __forceinline__ unsigned long long ffma2(unsigned long long a,
                                                    unsigned long long b,
                                                    unsigned long long c) {
    unsigned long long d;
    asm("fma.rn.f32x2 %0, %1, %2, %3;" : "=l"(d) : "l"(a), "l"(b), "l"(c));
    return d;
}
__device__ __forceinline__ float2 unpack2(unsigned long long v) {
    float2 f;
    asm("mov.b64 {%0, %1}, %2;" : "=f"(f.x), "=f"(f.y) : "l"(v));
    return f;
}

// ---------------- weight folding: A0 = W0 - W2, A1 = W1, A2 = 2*W2 ----------------
__global__ void prepA_kernel(const float* __restrict__ W) {
    int idx = blockIdx.x * blockDim.x + threadIdx.x;
    if (idx < 3 * 4096) {
        int i = idx >> 12, r = idx & 4095;
        const float* Wi = W + i * 3 * 4096;
        float w0 = Wi[r], w1 = Wi[4096 + r], w2 = Wi[8192 + r];
        float* Ai = g_A + i * 3 * 4096;
        Ai[r]        = w0 - w2;
        Ai[4096 + r] = w1;
        Ai[8192 + r] = 2.0f * w2;
    }
}

__global__ void zero_kernel(int n) {
    int i = blockIdx.x * blockDim.x + threadIdx.x;
    if (i < n) { g_srcdeg[i] = 0; g_rowcnt[i] = 0; g_cursor[i] = 0; }
}

__global__ void count_kernel(const int* __restrict__ src, const int* __restrict__ dst, int e) {
    int i = blockIdx.x * blockDim.x + threadIdx.x;
    if (i < e) {
        atomicAdd(&g_srcdeg[src[i]], 1);
        atomicAdd(&g_rowcnt[dst[i]], 1);
    }
}

__global__ void dinv_kernel(int n) {
    int i = blockIdx.x * blockDim.x + threadIdx.x;
    if (i < n) {
        int d = g_srcdeg[i];
        g_dinv[i] = (d > 0) ? rsqrtf((float)d) : 0.0f;
    }
}

// single-block exclusive scan of g_rowcnt -> g_rowptr
__global__ void scan_kernel(int n) {
    __shared__ int warp_tot[32];
    __shared__ int carry_sh;
    int t = threadIdx.x, lane = t & 31, wid = t >> 5;
    if (t == 0) carry_sh = 0;
    __syncthreads();
    for (int base = 0; base < n; base += 1024) {
        int i = base + t;
        int v = (i < n) ? g_rowcnt[i] : 0;
        int x = v;
        #pragma unroll
        for (int off = 1; off < 32; off <<= 1) {
            int y = __shfl_up_sync(0xffffffffu, x, off);
            if (lane >= off) x += y;
        }
        if (lane == 31) warp_tot[wid] = x;
        __syncthreads();
        if (wid == 0) {
            int wt = warp_tot[lane];
            #pragma unroll
            for (int off = 1; off < 32; off <<= 1) {
                int y = __shfl_up_sync(0xffffffffu, wt, off);
                if (lane >= off) wt += y;
            }
            warp_tot[lane] = wt;
        }
        __syncthreads();
        int wp = (wid > 0) ? warp_tot[wid - 1] : 0;
        if (i < n) g_rowptr[i] = carry_sh + wp + x - v;
        __syncthreads();
        if (t == 0) carry_sh += warp_tot[31];
        __syncthreads();
    }
    if (t == 0) g_rowptr[n] = carry_sh;
}

__global__ void scatter_kernel(const int* __restrict__ src, const int* __restrict__ dst, int e) {
    int i = blockIdx.x * blockDim.x + threadIdx.x;
    if (i < e) {
        int s = src[i], d = dst[i];
        float w = -g_dinv[s] * g_dinv[d];
        int pos = g_rowptr[d] + atomicAdd(&g_cursor[d], 1);
        g_csr[pos] = make_int2(s, __float_as_int(w));
    }
}

// ---------------- SpMM: Y[dst] = sum_e w * X[src]  (16 threads per row) ----------------
__global__ __launch_bounds__(256) void spmm_kernel(int mode, int n) {
    const float* __restrict__ X = mode ? g_T1 : g_H;
    float* __restrict__ Y       = mode ? g_T2 : g_T1;
    int gid  = blockIdx.x * blockDim.x + threadIdx.x;
    int row  = gid >> 4;
    int lane = gid & 15;
    if (row >= n) return;
    int beg = g_rowptr[row], end = g_rowptr[row + 1];
    float4 a0 = make_float4(0.f, 0.f, 0.f, 0.f);
    float4 a1 = make_float4(0.f, 0.f, 0.f, 0.f);
    int e = beg;
    for (; e + 2 <= end; e += 2) {
        int2 c0 = g_csr[e];
        int2 c1 = g_csr[e + 1];
        float4 v0 = *(const float4*)(X + c0.x * HIDDIM + lane * 4);
        float4 v1 = *(const float4*)(X + c1.x * HIDDIM + lane * 4);
        float w0 = __int_as_float(c0.y), w1 = __int_as_float(c1.y);
        a0.x += w0 * v0.x; a0.y += w0 * v0.y; a0.z += w0 * v0.z; a0.w += w0 * v0.w;
        a1.x += w1 * v1.x; a1.y += w1 * v1.y; a1.z += w1 * v1.z; a1.w += w1 * v1.w;
    }
    if (e < end) {
        int2 c0 = g_csr[e];
        float4 v0 = *(const float4*)(X + c0.x * HIDDIM + lane * 4);
        float w0 = __int_as_float(c0.y);
        a0.x += w0 * v0.x; a0.y += w0 * v0.y; a0.z += w0 * v0.z; a0.w += w0 * v0.w;
    }
    float4 r;
    r.x = a0.x + a1.x; r.y = a0.y + a1.y; r.z = a0.z + a1.z; r.w = a0.w + a1.w;
    *(float4*)(Y + row * HIDDIM + lane * 4) = r;
}

// ---------------- input GEMM: g_H = x @ W_in + b_in  (32 rows/block) ----------------
__global__ __launch_bounds__(256) void ingemm_kernel(const float* __restrict__ x,
                                                     const float* __restrict__ Win,
                                                     const float* __restrict__ bin, int n) {
    __shared__ float sW[16 * 64];
    __shared__ float xt[16 * 33];
    __shared__ float so[32 * 65];
    int t = threadIdx.x, lane = t & 31, wg = t >> 5;
    int row0 = blockIdx.x * 32;
    for (int idx = t; idx < 1024; idx += 256) sW[idx] = Win[idx];
    for (int idx = t; idx < 512; idx += 256) {
        int r = idx >> 4, k = idx & 15;
        int row = row0 + r;
        xt[k * 33 + r] = (row < n) ? x[row * 16 + k] : 0.0f;
    }
    __syncthreads();
    float acc[8] = {0, 0, 0, 0, 0, 0, 0, 0};
    #pragma unroll
    for (int k = 0; k < 16; k++) {
        float xv = xt[k * 33 + lane];
        float4 w0 = *(const float4*)&sW[k * 64 + wg * 8];
        float4 w1 = *(const float4*)&sW[k * 64 + wg * 8 + 4];
        acc[0] += xv * w0.x; acc[1] += xv * w0.y; acc[2] += xv * w0.z; acc[3] += xv * w0.w;
        acc[4] += xv * w1.x; acc[5] += xv * w1.y; acc[6] += xv * w1.z; acc[7] += xv * w1.w;
    }
    #pragma unroll
    for (int u = 0; u < 8; u++) {
        int j = wg * 8 + u;
        so[lane * 65 + j] = acc[u] + bin[j];
    }
    __syncthreads();
    int r = t >> 3, c = (t & 7) * 8;
    int row = row0 + r;
    if (row < n) {
        float4 v0, v1;
        v0.x = so[r*65+c+0]; v0.y = so[r*65+c+1]; v0.z = so[r*65+c+2]; v0.w = so[r*65+c+3];
        v1.x = so[r*65+c+4]; v1.y = so[r*65+c+5]; v1.z = so[r*65+c+6]; v1.w = so[r*65+c+7];
        *(float4*)(g_H + row * 64 + c)     = v0;
        *(float4*)(g_H + row * 64 + c + 4) = v1;
    }
}

// ---------------- fused layer (128 rows/block, f32x2 FMA, fused out-GEMM on last) ----
// H = LN(relu(H@A0 + T1@A1 + T2@A2 + cb) + H) ; if last: out = H@Wout + bout (no g_H store)
#define LK_HT_STRIDE 129
#define LK_HT_FLOATS (64 * LK_HT_STRIDE)          // 8256
#define LK_SMEM_BYTES ((LK_HT_FLOATS + 4096) * 4) // 49408

__global__ __launch_bounds__(256) void layer_kernel(int layer,
                                                    const float* __restrict__ cb,
                                                    const float* __restrict__ lg,
                                                    const float* __restrict__ lbeta,
                                                    const float* __restrict__ Wout,
                                                    const float* __restrict__ bout,
                                                    float* __restrict__ out,
                                                    int last, int n) {
    extern __shared__ float smem[];
    float* ht = smem;                 // [64][129] transposed tile
    float* sA = smem + LK_HT_FLOATS;  // [64][64] current weight matrix
    __shared__ float sWout[260];

    int t = threadIdx.x;
    int c8 = (t & 7) * 8;             // column group (8 cols)
    int rg = t >> 3;                  // row group (4 rows): rows rg*4..rg*4+3
    int row0 = blockIdx.x * 128;
    const float* __restrict__ A = g_A + layer * 12288;

    if (last) {
        sWout[t] = Wout[t];           // 256 threads cover 64x4
        if (t < 4) sWout[256 + t] = bout[t];
    }

    unsigned long long acc[4][4];
    #pragma unroll
    for (int i = 0; i < 4; i++)
        #pragma unroll
        for (int j = 0; j < 4; j++) acc[i][j] = pack2(0.0f, 0.0f);

    #pragma unroll
    for (int pass = 0; pass < 3; pass++) {
        const float* __restrict__ S = (pass == 0) ? g_H : ((pass == 1) ? g_T1 : g_T2);
        // stage weights
        for (int idx = t; idx < 1024; idx += 256)
            ((float4*)sA)[idx] = ((const float4*)(A + pass * 4096))[idx];
        // stage tile transposed: ht[k][r] = S[row0+r][k]
        for (int idx = t; idx < 2048; idx += 256) {
            int r = idx >> 4, k4 = (idx & 15) * 4;
            int grow = row0 + r;
            float4 v = make_float4(0.f, 0.f, 0.f, 0.f);
            if (grow < n) v = *(const float4*)(S + grow * 64 + k4);
            int b = k4 * LK_HT_STRIDE + r;
            ht[b]                    = v.x;
            ht[b + LK_HT_STRIDE]     = v.y;
            ht[b + 2 * LK_HT_STRIDE] = v.z;
            ht[b + 3 * LK_HT_STRIDE] = v.w;
        }
        __syncthreads();
        #pragma unroll 8
        for (int k = 0; k < 64; k++) {
            unsigned long long h2[4];
            #pragma unroll
            for (int i = 0; i < 4; i++) {
                float hv = ht[k * LK_HT_STRIDE + rg * 4 + i];
                h2[i] = pack2(hv, hv);
            }
            float4 wa = *(const float4*)&sA[k * 64 + c8];
            float4 wb = *(const float4*)&sA[k * 64 + c8 + 4];
            unsigned long long w2[4];
            w2[0] = pack2(wa.x, wa.y); w2[1] = pack2(wa.z, wa.w);
            w2[2] = pack2(wb.x, wb.y); w2[3] = pack2(wb.z, wb.w);
            #pragma unroll
            for (int i = 0; i < 4; i++)
                #pragma unroll
                for (int j = 0; j < 4; j++)
                    acc[i][j] = ffma2(h2[i], w2[j], acc[i][j]);
        }
        __syncthreads();
    }

    // ---- epilogue: bias + relu + residual + layernorm (+ fused out-GEMM) ----
    float cbv[8], lgv[8], lbv[8];
    {
        float4 a0 = *(const float4*)(cb + c8),    a1 = *(const float4*)(cb + c8 + 4);
        float4 g0 = *(const float4*)(lg + c8),    g1 = *(const float4*)(lg + c8 + 4);
        float4 b0 = *(const float4*)(lbeta + c8), b1 = *(const float4*)(lbeta + c8 + 4);
        cbv[0]=a0.x;cbv[1]=a0.y;cbv[2]=a0.z;cbv[3]=a0.w;cbv[4]=a1.x;cbv[5]=a1.y;cbv[6]=a1.z;cbv[7]=a1.w;
        lgv[0]=g0.x;lgv[1]=g0.y;lgv[2]=g0.z;lgv[3]=g0.w;lgv[4]=g1.x;lgv[5]=g1.y;lgv[6]=g1.z;lgv[7]=g1.w;
        lbv[0]=b0.x;lbv[1]=b0.y;lbv[2]=b0.z;lbv[3]=b0.w;lbv[4]=b1.x;lbv[5]=b1.y;lbv[6]=b1.z;lbv[7]=b1.w;
    }

    #pragma unroll
    for (int i = 0; i < 4; i++) {
        int grow = row0 + rg * 4 + i;
        float hres[8];
        if (grow < n) {
            float4 r0 = *(const float4*)(g_H + grow * 64 + c8);
            float4 r1 = *(const float4*)(g_H + grow * 64 + c8 + 4);
            hres[0]=r0.x;hres[1]=r0.y;hres[2]=r0.z;hres[3]=r0.w;
            hres[4]=r1.x;hres[5]=r1.y;hres[6]=r1.z;hres[7]=r1.w;
        } else {
            #pragma unroll
            for (int u = 0; u < 8; u++) hres[u] = 0.0f;
        }
        float val[8];
        #pragma unroll
        for (int j = 0; j < 4; j++) {
            float2 a = unpack2(acc[i][j]);
            val[2*j]   = fmaxf(a.x + cbv[2*j],   0.0f) + hres[2*j];
            val[2*j+1] = fmaxf(a.y + cbv[2*j+1], 0.0f) + hres[2*j+1];
        }
        float s = 0.0f;
        #pragma unroll
        for (int u = 0; u < 8; u++) s += val[u];
        #pragma unroll
        for (int m = 1; m < 8; m <<= 1) s += __shfl_xor_sync(0xffffffffu, s, m);
        float mu = s * (1.0f / 64.0f);
        float q = 0.0f;
        #pragma unroll
        for (int u = 0; u < 8; u++) { float d = val[u] - mu; q += d * d; }
        #pragma unroll
        for (int m = 1; m < 8; m <<= 1) q += __shfl_xor_sync(0xffffffffu, q, m);
        float rs = rsqrtf(q * (1.0f / 64.0f) + LN_EPS);

        float o[8];
        #pragma unroll
        for (int u = 0; u < 8; u++)
            o[u] = (val[u] - mu) * rs * lgv[u] + lbv[u];

        if (!last) {
            if (grow < n) {
                *(float4*)(g_H + grow * 64 + c8)     = make_float4(o[0], o[1], o[2], o[3]);
                *(float4*)(g_H + grow * 64 + c8 + 4) = make_float4(o[4], o[5], o[6], o[7]);
            }
        } else {
            float4 oa = make_float4(0.f, 0.f, 0.f, 0.f);
            #pragma unroll
            for (int u = 0; u < 8; u++) {
                const float* wr = &sWout[(c8 + u) * 4];
                oa.x += o[u] * wr[0]; oa.y += o[u] * wr[1];
                oa.z += o[u] * wr[2]; oa.w += o[u] * wr[3];
            }
            #pragma unroll
            for (int m = 1; m < 8; m <<= 1) {
                oa.x += __shfl_xor_sync(0xffffffffu, oa.x, m);
                oa.y += __shfl_xor_sync(0xffffffffu, oa.y, m);
                oa.z += __shfl_xor_sync(0xffffffffu, oa.z, m);
                oa.w += __shfl_xor_sync(0xffffffffu, oa.w, m);
            }
            if ((t & 7) == 0 && grow < n) {
                oa.x += sWout[256]; oa.y += sWout[257]; oa.z += sWout[258]; oa.w += sWout[259];
                *(float4*)(out + grow * 4) = oa;
            }
        }
    }
}

// ---------------- launch ----------------
extern "C" void kernel_launch(void* const* d_in, const int* in_sizes, int n_in,
                              void* d_out, int out_size) {
    const float *x = 0, *Win = 0, *bin = 0, *chW = 0, *Wout = 0, *bout = 0;
    const float *p192[3] = {0, 0, 0};
    const int* ei = 0;
    int n192 = 0, e2 = 0, nx = 0;
    for (int i = 0; i < n_in; i++) {
        int sz = in_sizes[i];
        if      (sz == 1600000) { ei = (const int*)d_in[i]; e2 = sz; }
        else if (sz == 800000)  { x = (const float*)d_in[i]; nx = sz; }
        else if (sz == 1024)    Win  = (const float*)d_in[i];
        else if (sz == 64)      bin  = (const float*)d_in[i];
        else if (sz == 36864)   chW  = (const float*)d_in[i];
        else if (sz == 256)     Wout = (const float*)d_in[i];
        else if (sz == 4)       bout = (const float*)d_in[i];
        else if (sz == 192 && n192 < 3) p192[n192++] = (const float*)d_in[i];
    }
    const float* chb = p192[0];
    const float* lng = p192[1];
    const float* lnb = p192[2];
    float* out = (float*)d_out;

    int n = nx / 16;
    int e = e2 / 2;
    const int* src = ei;
    const int* dst = ei + e;

    // one-time host resources (lazy; host-side only, no device memory)
    static cudaStream_t s_fork = 0;
    static cudaEvent_t  s_ev1 = 0, s_ev2 = 0;
    static int s_attr_done = 0;
    if (!s_fork) {
        cudaStreamCreateWithFlags(&s_fork, cudaStreamNonBlocking);
        cudaEventCreateWithFlags(&s_ev1, cudaEventDisableTiming);
        cudaEventCreateWithFlags(&s_ev2, cudaEventDisableTiming);
    }
    if (!s_attr_done) {
        cudaFuncSetAttribute(layer_kernel, cudaFuncAttributeMaxDynamicSharedMemorySize,
                             LK_SMEM_BYTES);
        s_attr_done = 1;
    }

    int ingemm_blocks = (n + 31) / 32;
    int layer_blocks  = (n + 127) / 128;
    int spmm_blocks   = (n * 16 + 255) / 256;

    // Fork: {prepA, ingemm} run concurrently with the CSR-build chain.
    cudaEventRecord(s_ev1, 0);
    cudaStreamWaitEvent(s_fork, s_ev1, 0);
    prepA_kernel<<<(3 * 4096 + 255) / 256, 256, 0, s_fork>>>(chW);
    ingemm_kernel<<<ingemm_blocks, 256, 0, s_fork>>>(x, Win, bin, n);
    cudaEventRecord(s_ev2, s_fork);

    // CSR build (default stream)
    zero_kernel<<<(n + 255) / 256, 256>>>(n);
    count_kernel<<<(e + 255) / 256, 256>>>(src, dst, e);
    dinv_kernel<<<(n + 255) / 256, 256>>>(n);
    scan_kernel<<<1, 1024>>>(n);
    scatter_kernel<<<(e + 255) / 256, 256>>>(src, dst, e);

    // Join
    cudaStreamWaitEvent((cudaStream_t)0, s_ev2, 0);

    for (int i = 0; i < 3; i++) {
        spmm_kernel<<<spmm_blocks, 256>>>(0, n);  // T1 = L_hat @ H
        spmm_kernel<<<spmm_blocks, 256>>>(1, n);  // T2 = L_hat @ T1
        layer_kernel<<<layer_blocks, 256, LK_SMEM_BYTES>>>(
            i, chb + i * 64, lng + i * 64, lnb + i * 64,
            Wout, bout, out, (i == 2) ? 1 : 0, n);
    }
}